// round 5
// baseline (speedup 1.0000x reference)
#include <cuda_runtime.h>

// ---------------------------------------------------------------------------
// LieSpline: SE(3) cubic B-spline interpolation.  B=32, N=2048, K=32.
//
// Kernel 1: per padded delta j (0..N): se3_log(inv(P[j])P[j+1]) + lane-
//   invariant precomputes for exp(w*delta) + the padded base pose, 6 float4:
//     r0: tau | nd    r1: U | 2/nd^2   r2: C1 | 1/nd^3
//     r3: C2 | 0      r4: pose_t | 0   r5: pose_q
// Kernel 2: warp = (b, 2 consecutive segments), lane = time sample (K==32).
//   Segments A and B run the SAME formula on different records, so all
//   FMA/MUL/ADD are executed as packed f32x2 (Blackwell FFMA2) — one
//   instruction computes both segments.  Sign flips via XOR on the packed
//   64-bit value (ALU pipe, which is idle).
// ---------------------------------------------------------------------------

#define LS_B 32
#define LS_N 2048
#define LS_J (LS_N + 1)   // 2049 deltas per batch
#define REC 6             // float4s per delta record
#define LS_S (LS_N - 1)   // 2047 segments
#define LS_M 1024         // segment-pairs per batch

__device__ float4 g_pre[LS_B * LS_J * REC];   // 6.3 MB scratch

// ---------------- scalar helpers (kernel 1) ----------------
__device__ __forceinline__ float3 f3(float x, float y, float z) {
    return make_float3(x, y, z);
}
__device__ __forceinline__ float3 cross3(const float3 a, const float3 b) {
    return make_float3(a.y * b.z - a.z * b.y,
                       a.z * b.x - a.x * b.z,
                       a.x * b.y - a.y * b.x);
}
__device__ __forceinline__ float dot3(const float3 a, const float3 b) {
    return a.x * b.x + a.y * b.y + a.z * b.z;
}
__device__ __forceinline__ float3 qrot(const float4 q, const float3 v) {
    float3 qv = f3(q.x, q.y, q.z);
    float3 t = cross3(qv, v);
    t.x *= 2.0f; t.y *= 2.0f; t.z *= 2.0f;
    float3 c = cross3(qv, t);
    return f3(v.x + q.w * t.x + c.x,
              v.y + q.w * t.y + c.y,
              v.z + q.w * t.z + c.z);
}
__device__ __forceinline__ float4 qmul(const float4 a, const float4 b) {
    return make_float4(
        a.w * b.x + a.x * b.w + a.y * b.z - a.z * b.y,
        a.w * b.y + a.y * b.w + a.z * b.x - a.x * b.z,
        a.w * b.z + a.z * b.w + a.x * b.y - a.y * b.x,
        a.w * b.w - a.x * b.x - a.y * b.y - a.z * b.z);
}

// ---------------- packed f32x2 helpers (kernel 2) ----------------
typedef unsigned long long u64;
__device__ __forceinline__ u64 pk2(float lo, float hi) {
    u64 r; asm("mov.b64 %0, {%1, %2};" : "=l"(r) : "f"(lo), "f"(hi)); return r;
}
__device__ __forceinline__ void unpk2(u64 v, float& lo, float& hi) {
    asm("mov.b64 {%0, %1}, %2;" : "=f"(lo), "=f"(hi) : "l"(v));
}
__device__ __forceinline__ u64 f2mul(u64 a, u64 b) {
    u64 r; asm("mul.rn.f32x2 %0, %1, %2;" : "=l"(r) : "l"(a), "l"(b)); return r;
}
__device__ __forceinline__ u64 f2add(u64 a, u64 b) {
    u64 r; asm("add.rn.f32x2 %0, %1, %2;" : "=l"(r) : "l"(a), "l"(b)); return r;
}
__device__ __forceinline__ u64 f2fma(u64 a, u64 b, u64 c) {
    u64 r; asm("fma.rn.f32x2 %0, %1, %2, %3;" : "=l"(r) : "l"(a), "l"(b), "l"(c)); return r;
}
__device__ __forceinline__ u64 f2neg(u64 a) { return a ^ 0x8000000080000000ULL; }

struct V3p { u64 x, y, z; };
struct X2 { V3p t; u64 qx, qy, qz, qw; };

// compose: R = P * Q  (both packed)
__device__ __forceinline__ X2 compose2(const X2& P, const X2& Q) {
    u64 nx = f2neg(P.qx), ny = f2neg(P.qy), nz = f2neg(P.qz);
    // c = 2 * cross(qv, Q.t)
    u64 cx = f2fma(P.qy, Q.t.z, f2mul(nz, Q.t.y));
    u64 cy = f2fma(P.qz, Q.t.x, f2mul(nx, Q.t.z));
    u64 cz = f2fma(P.qx, Q.t.y, f2mul(ny, Q.t.x));
    cx = f2add(cx, cx); cy = f2add(cy, cy); cz = f2add(cz, cz);
    // d = cross(qv, c)
    u64 dx = f2fma(P.qy, cz, f2mul(nz, cy));
    u64 dy = f2fma(P.qz, cx, f2mul(nx, cz));
    u64 dz = f2fma(P.qx, cy, f2mul(ny, cx));
    X2 r;
    // r.t = P.t + (Q.t + qw*c + d)
    r.t.x = f2add(P.t.x, f2add(Q.t.x, f2fma(P.qw, cx, dx)));
    r.t.y = f2add(P.t.y, f2add(Q.t.y, f2fma(P.qw, cy, dy)));
    r.t.z = f2add(P.t.z, f2add(Q.t.z, f2fma(P.qw, cz, dz)));
    // r.q = P.q * Q.q
    r.qx = f2fma(P.qw, Q.qx, f2fma(P.qx, Q.qw, f2fma(P.qy, Q.qz, f2mul(nz, Q.qy))));
    r.qy = f2fma(P.qw, Q.qy, f2fma(P.qy, Q.qw, f2fma(P.qz, Q.qx, f2mul(nx, Q.qz))));
    r.qz = f2fma(P.qw, Q.qz, f2fma(P.qz, Q.qw, f2fma(P.qx, Q.qy, f2mul(ny, Q.qx))));
    r.qw = f2fma(P.qw, Q.qw, f2fma(nx, Q.qx, f2fma(ny, Q.qy, f2mul(nz, Q.qz))));
    return r;
}

// packed exp(wk * delta): records A (seg0) and B (seg1), same weight wk
__device__ __forceinline__ X2 expw2(
    const float4& Aa0, const float4& Aa1, const float4& Aa2, const float4& Aa3,
    const float4& Ba0, const float4& Ba1, const float4& Ba2, const float4& Ba3,
    float wk)
{
    float tha = wk * Aa0.w;
    float thb = wk * Ba0.w;
    float sa, ca, sb, cb;
    __sincosf(0.5f * tha, &sa, &ca);
    __sincosf(0.5f * thb, &sb, &cb);
    u64 sh = pk2(sa, sb), ch = pk2(ca, cb);
    u64 theta = pk2(tha, thb);
    u64 alpha = f2mul(f2mul(sh, sh), pk2(Aa1.w, Ba1.w));         // (1-cos)/nd^2
    u64 beta  = f2mul(f2fma(f2neg(f2add(sh, sh)), ch, theta),
                      pk2(Aa2.w, Ba2.w));                         // (th-sin)/nd^3
    u64 wk2 = pk2(wk, wk);
    X2 r;
    r.t.x = f2fma(beta, pk2(Aa3.x, Ba3.x),
             f2fma(alpha, pk2(Aa2.x, Ba2.x), f2mul(wk2, pk2(Aa0.x, Ba0.x))));
    r.t.y = f2fma(beta, pk2(Aa3.y, Ba3.y),
             f2fma(alpha, pk2(Aa2.y, Ba2.y), f2mul(wk2, pk2(Aa0.y, Ba0.y))));
    r.t.z = f2fma(beta, pk2(Aa3.z, Ba3.z),
             f2fma(alpha, pk2(Aa2.z, Ba2.z), f2mul(wk2, pk2(Aa0.z, Ba0.z))));
    r.qx = f2mul(sh, pk2(Aa1.x, Ba1.x));
    r.qy = f2mul(sh, pk2(Aa1.y, Ba1.y));
    r.qz = f2mul(sh, pk2(Aa1.z, Ba1.z));
    r.qw = ch;
    return r;
}

// ---------------------------------------------------------------------------
// Kernel 1: per-(b, j) relative-pose log + precompute
// ---------------------------------------------------------------------------
__global__ void __launch_bounds__(256) k_delta(const float* __restrict__ poses) {
    int idx = blockIdx.x * blockDim.x + threadIdx.x;
    if (idx >= LS_B * LS_J) return;
    int b = idx / LS_J;
    int j = idx - b * LS_J;
    float4* o = g_pre + (size_t)idx * REC;
    const float* pbase = poses + (size_t)b * LS_N * 7;

    int pj = j > 0 ? j - 1 : 0;
    const float* pr = pbase + (size_t)pj * 7;
    float3 t0 = f3(pr[0], pr[1], pr[2]);
    float4 q0 = make_float4(pr[3], pr[4], pr[5], pr[6]);
    o[4] = make_float4(t0.x, t0.y, t0.z, 0.f);
    o[5] = q0;

    if (j == 0 || j == LS_N) {
        float4 z = make_float4(0.f, 0.f, 0.f, 0.f);
        o[0] = z; o[1] = z; o[2] = z; o[3] = z;
        return;
    }
    const float* pr1 = pr + 7;
    float3 t1 = f3(pr1[0], pr1[1], pr1[2]);
    float4 q1 = make_float4(pr1[3], pr1[4], pr1[5], pr1[6]);

    float4 qi = make_float4(-q0.x, -q0.y, -q0.z, q0.w);
    float3 dt = f3(t1.x - t0.x, t1.y - t0.y, t1.z - t0.z);
    float3 t  = qrot(qi, dt);
    float4 q  = qmul(qi, q1);

    float n2 = q.x * q.x + q.y * q.y + q.z * q.z;
    bool small = n2 < 1e-12f;
    float ns = small ? 1.0f : n2;
    float rn = rsqrtf(ns);
    float n  = ns * rn;
    float factor;
    if (small) {
        float iw = __fdividef(1.0f, q.w);
        factor = 2.0f * iw - (2.0f / 3.0f) * n2 * iw * iw * iw;
    } else {
        factor = 2.0f * atan2f(n, q.w) * rn;
    }
    float3 phi = f3(factor * q.x, factor * q.y, factor * q.z);

    float t2 = dot3(phi, phi);
    bool sm2 = t2 < 1e-12f;
    float t2s = sm2 ? 1.0f : t2;
    float rth = rsqrtf(t2s);
    float theta = t2s * rth;
    float s, cth;
    __sincosf(theta, &s, &cth);
    float s_safe = (fabsf(s) < 1e-6f) ? 1e-6f : s;
    float c;
    if (sm2) {
        c = (1.0f / 12.0f) + t2 * (1.0f / 720.0f);
    } else {
        c = rth * rth - __fdividef(1.0f + cth, 2.0f * theta * s_safe);
    }
    float3 x1 = cross3(phi, t);
    float3 x2 = cross3(phi, x1);
    float3 tau = f3(t.x - 0.5f * x1.x + c * x2.x,
                    t.y - 0.5f * x1.y + c * x2.y,
                    t.z - 0.5f * x1.z + c * x2.z);

    float nd2 = dot3(phi, phi);
    if (nd2 < 1e-24f) {
        o[0] = make_float4(tau.x, tau.y, tau.z, 0.f);
        float4 z = make_float4(0.f, 0.f, 0.f, 0.f);
        o[1] = z; o[2] = z; o[3] = z;
        return;
    }
    float rnd = rsqrtf(nd2);
    float nd  = nd2 * rnd;
    float K2  = 2.0f * rnd * rnd;
    float rn3 = rnd * rnd * rnd;
    float3 U  = f3(phi.x * rnd, phi.y * rnd, phi.z * rnd);
    float3 C1 = cross3(phi, tau);
    float3 C2 = cross3(phi, C1);
    o[0] = make_float4(tau.x, tau.y, tau.z, nd);
    o[1] = make_float4(U.x, U.y, U.z, K2);
    o[2] = make_float4(C1.x, C1.y, C1.z, rn3);
    o[3] = make_float4(C2.x, C2.y, C2.z, 0.f);
}

// ---------------------------------------------------------------------------
// Kernel 2: warp = (b, segment pair m -> segments 2m, 2m+1), lane = sample k.
// ---------------------------------------------------------------------------
__global__ void __launch_bounds__(256) k_spline(const float* __restrict__ timev,
                                                float* __restrict__ out) {
    int w    = threadIdx.x >> 5;
    int lane = threadIdx.x & 31;
    int gp = blockIdx.x * 8 + w;
    if (gp >= LS_B * LS_M) return;
    int b = gp >> 10;
    int m = gp & (LS_M - 1);
    int s0 = 2 * m;
    bool tail = (s0 + 1 >= LS_S);

    float u  = __ldg(timev + lane);
    float u2 = u * u;
    float u3 = u2 * u;
    const float w0 = (5.0f + 3.0f * u - 3.0f * u2 + u3) * (1.0f / 6.0f);
    const float w1 = (1.0f + 3.0f * u + 3.0f * u2 - 2.0f * u3) * (1.0f / 6.0f);
    const float w2 = u3 * (1.0f / 6.0f);

    const float4* base = g_pre + ((size_t)b * LS_J) * REC;
    const float4* R0 = base + (size_t)s0 * REC;
    const float4* R1 = R0 + REC;
    const float4* R2 = R0 + 2 * REC;
    int s3 = tail ? (s0 + 2) : (s0 + 3);
    const float4* R3 = base + (size_t)s3 * REC;

    float4 d0a = R0[0], d0b = R0[1], d0c = R0[2], d0d = R0[3];
    float4 d1a = R1[0], d1b = R1[1], d1c = R1[2], d1d = R1[3];
    float4 d2a = R2[0], d2b = R2[1], d2c = R2[2], d2d = R2[3];
    float4 d3a = R3[0], d3b = R3[1], d3c = R3[2], d3d = R3[3];
    float4 p0t = R0[4], p0q = R0[5];
    float4 p1t = R1[4], p1q = R1[5];

    // packed exps: step i uses record s0+i for segA, s0+1+i for segB
    X2 A0 = expw2(d0a, d0b, d0c, d0d, d1a, d1b, d1c, d1d, w0);
    X2 A1 = expw2(d1a, d1b, d1c, d1d, d2a, d2b, d2c, d2d, w1);
    X2 A2 = expw2(d2a, d2b, d2c, d2d, d3a, d3b, d3c, d3d, w2);

    // packed base pose
    X2 P;
    P.t.x = pk2(p0t.x, p1t.x); P.t.y = pk2(p0t.y, p1t.y); P.t.z = pk2(p0t.z, p1t.z);
    P.qx = pk2(p0q.x, p1q.x); P.qy = pk2(p0q.y, p1q.y);
    P.qz = pk2(p0q.z, p1q.z); P.qw = pk2(p0q.w, p1q.w);

    // out = (P·A0)·(A1·A2)  — two independent composes then a join
    X2 O = compose2(compose2(P, A0), compose2(A1, A2));

    // unpack + stage through shared; 448 contiguous floats per warp
    __shared__ __align__(16) float sm[8 * 448];
    float* smw  = sm + w * 448;
    float* smw2 = smw + 224;
    int o7 = lane * 7;
    float va, vb;
    unpk2(O.t.x, va, vb); smw[o7 + 0] = va; smw2[o7 + 0] = vb;
    unpk2(O.t.y, va, vb); smw[o7 + 1] = va; smw2[o7 + 1] = vb;
    unpk2(O.t.z, va, vb); smw[o7 + 2] = va; smw2[o7 + 2] = vb;
    unpk2(O.qx,  va, vb); smw[o7 + 3] = va; smw2[o7 + 3] = vb;
    unpk2(O.qy,  va, vb); smw[o7 + 4] = va; smw2[o7 + 4] = vb;
    unpk2(O.qz,  va, vb); smw[o7 + 5] = va; smw2[o7 + 5] = vb;
    unpk2(O.qw,  va, vb); smw[o7 + 6] = va; smw2[o7 + 6] = vb;
    __syncwarp();

    const float4* sm4 = (const float4*)smw;
    size_t pair0 = (size_t)b * LS_S + s0;
    float4* ob4 = (float4*)(out + pair0 * 224);
    if (!tail) {
        ob4[lane]      = sm4[lane];
        ob4[lane + 32] = sm4[lane + 32];
        ob4[lane + 64] = sm4[lane + 64];
        if (lane < 16) ob4[lane + 96] = sm4[lane + 96];
    } else {
        ob4[lane] = sm4[lane];
        if (lane < 24) ob4[lane + 32] = sm4[lane + 32];
    }
}

extern "C" void kernel_launch(void* const* d_in, const int* in_sizes, int n_in,
                              void* d_out, int out_size) {
    (void)n_in; (void)out_size;
    const float* poses = (const float*)d_in[0];
    const float* timev = (const float*)d_in[1];
    float* out = (float*)d_out;

    int tot1 = LS_B * LS_J;
    k_delta<<<(tot1 + 255) / 256, 256>>>(poses);

    int tot2 = LS_B * LS_M;
    k_spline<<<(tot2 + 7) / 8, 256>>>(timev, out);
}

// round 6
// speedup vs baseline: 1.3372x; 1.3372x over previous
#include <cuda_runtime.h>

// ---------------------------------------------------------------------------
// LieSpline: SE(3) cubic B-spline interpolation.  B=32, N=2048, K=32.
//
// Kernel 1: per padded delta j (0..N): se3_log(inv(P[j])P[j+1]) + lane-
//   invariant precomputes for exp(w*delta) + the padded base pose, 6 float4:
//     r0: tau | nd   r1: U | 0   r2: K2*C1 | 0   r3: rn3*C2 | 0
//     r4: pose_t | 0   r5: pose_q
//   so that exp(w*d): theta=w*nd, sincos(theta/2), alpha=sh^2,
//     beta=theta-2*sh*ch, At = w*tau + alpha*C1' + beta*C2', Aq=(sh*U, ch).
// Kernel 2: warp = (b, 2 consecutive segments), lane = time sample (K==32).
//   Serial-interleaved: each record is loaded once and consumed immediately
//   by both segment chains -> small live set (high occupancy) while keeping
//   R4's halved record traffic.
// ---------------------------------------------------------------------------

#define LS_B 32
#define LS_N 2048
#define LS_J (LS_N + 1)   // 2049 deltas per batch
#define REC 6             // float4s per delta record
#define LS_S (LS_N - 1)   // 2047 segments
#define LS_M 1024         // segment-pairs per batch

__device__ float4 g_pre[LS_B * LS_J * REC];   // 6.3 MB scratch

__device__ __forceinline__ float3 f3(float x, float y, float z) {
    return make_float3(x, y, z);
}
__device__ __forceinline__ float3 cross3(const float3 a, const float3 b) {
    return make_float3(a.y * b.z - a.z * b.y,
                       a.z * b.x - a.x * b.z,
                       a.x * b.y - a.y * b.x);
}
__device__ __forceinline__ float dot3(const float3 a, const float3 b) {
    return a.x * b.x + a.y * b.y + a.z * b.z;
}
__device__ __forceinline__ float3 qrot(const float4 q, const float3 v) {
    float3 qv = f3(q.x, q.y, q.z);
    float3 t = cross3(qv, v);
    t.x *= 2.0f; t.y *= 2.0f; t.z *= 2.0f;
    float3 c = cross3(qv, t);
    return f3(v.x + q.w * t.x + c.x,
              v.y + q.w * t.y + c.y,
              v.z + q.w * t.z + c.z);
}
__device__ __forceinline__ float4 qmul(const float4 a, const float4 b) {
    return make_float4(
        a.w * b.x + a.x * b.w + a.y * b.z - a.z * b.y,
        a.w * b.y + a.y * b.w + a.z * b.x - a.x * b.z,
        a.w * b.z + a.z * b.w + a.x * b.y - a.y * b.x,
        a.w * b.w - a.x * b.x - a.y * b.y - a.z * b.z);
}

// ---------------------------------------------------------------------------
// Kernel 1: per-(b, j) relative-pose log + precompute
// ---------------------------------------------------------------------------
__global__ void __launch_bounds__(256) k_delta(const float* __restrict__ poses) {
    int idx = blockIdx.x * blockDim.x + threadIdx.x;
    if (idx >= LS_B * LS_J) return;
    int b = idx / LS_J;
    int j = idx - b * LS_J;
    float4* o = g_pre + (size_t)idx * REC;
    const float* pbase = poses + (size_t)b * LS_N * 7;

    int pj = j > 0 ? j - 1 : 0;
    const float* pr = pbase + (size_t)pj * 7;
    float3 t0 = f3(pr[0], pr[1], pr[2]);
    float4 q0 = make_float4(pr[3], pr[4], pr[5], pr[6]);
    o[4] = make_float4(t0.x, t0.y, t0.z, 0.f);
    o[5] = q0;

    if (j == 0 || j == LS_N) {
        float4 z = make_float4(0.f, 0.f, 0.f, 0.f);
        o[0] = z; o[1] = z; o[2] = z; o[3] = z;
        return;
    }
    const float* pr1 = pr + 7;
    float3 t1 = f3(pr1[0], pr1[1], pr1[2]);
    float4 q1 = make_float4(pr1[3], pr1[4], pr1[5], pr1[6]);

    float4 qi = make_float4(-q0.x, -q0.y, -q0.z, q0.w);
    float3 dt = f3(t1.x - t0.x, t1.y - t0.y, t1.z - t0.z);
    float3 t  = qrot(qi, dt);
    float4 q  = qmul(qi, q1);

    float n2 = q.x * q.x + q.y * q.y + q.z * q.z;
    bool small = n2 < 1e-12f;
    float ns = small ? 1.0f : n2;
    float rn = rsqrtf(ns);
    float n  = ns * rn;
    float factor;
    if (small) {
        float iw = __fdividef(1.0f, q.w);
        factor = 2.0f * iw - (2.0f / 3.0f) * n2 * iw * iw * iw;
    } else {
        factor = 2.0f * atan2f(n, q.w) * rn;
    }
    float3 phi = f3(factor * q.x, factor * q.y, factor * q.z);

    float t2 = dot3(phi, phi);
    bool sm2 = t2 < 1e-12f;
    float t2s = sm2 ? 1.0f : t2;
    float rth = rsqrtf(t2s);
    float theta = t2s * rth;
    float s, cth;
    __sincosf(theta, &s, &cth);
    float s_safe = (fabsf(s) < 1e-6f) ? 1e-6f : s;
    float c;
    if (sm2) {
        c = (1.0f / 12.0f) + t2 * (1.0f / 720.0f);
    } else {
        c = rth * rth - __fdividef(1.0f + cth, 2.0f * theta * s_safe);
    }
    float3 x1 = cross3(phi, t);
    float3 x2 = cross3(phi, x1);
    float3 tau = f3(t.x - 0.5f * x1.x + c * x2.x,
                    t.y - 0.5f * x1.y + c * x2.y,
                    t.z - 0.5f * x1.z + c * x2.z);

    float nd2 = dot3(phi, phi);
    if (nd2 < 1e-24f) {
        o[0] = make_float4(tau.x, tau.y, tau.z, 0.f);
        float4 z = make_float4(0.f, 0.f, 0.f, 0.f);
        o[1] = z; o[2] = z; o[3] = z;
        return;
    }
    float rnd = rsqrtf(nd2);         // 1/nd
    float nd  = nd2 * rnd;           // |phi|
    float K2  = 2.0f * rnd * rnd;    // 2/nd^2
    float rn3 = rnd * rnd * rnd;     // 1/nd^3
    float3 U  = f3(phi.x * rnd, phi.y * rnd, phi.z * rnd);
    float3 C1 = cross3(phi, tau);
    float3 C2 = cross3(phi, C1);
    o[0] = make_float4(tau.x, tau.y, tau.z, nd);
    o[1] = make_float4(U.x, U.y, U.z, 0.f);
    o[2] = make_float4(K2 * C1.x, K2 * C1.y, K2 * C1.z, 0.f);   // C1'
    o[3] = make_float4(rn3 * C2.x, rn3 * C2.y, rn3 * C2.z, 0.f); // C2'
}

// ---------------------------------------------------------------------------
// exp + in-place right-compose: T <- T * exp(wk * delta)
// record fields: a0 = tau|nd, a1 = U, a2 = C1', a3 = C2'
// ---------------------------------------------------------------------------
struct Xf { float3 t; float4 q; };

__device__ __forceinline__ void stepc(Xf& T,
                                      const float4 a0, const float4 a1,
                                      const float4 a2, const float4 a3,
                                      float wk) {
    float theta = wk * a0.w;
    float sh, ch;
    __sincosf(0.5f * theta, &sh, &ch);
    float alpha = sh * sh;                        // (1 - cos th)/2 *2 -> sh^2
    float beta  = fmaf(-(sh + sh), ch, theta);    // th - sin th
    float3 At = f3(fmaf(beta, a3.x, fmaf(alpha, a2.x, wk * a0.x)),
                   fmaf(beta, a3.y, fmaf(alpha, a2.y, wk * a0.y)),
                   fmaf(beta, a3.z, fmaf(alpha, a2.z, wk * a0.z)));
    float4 Aq = make_float4(sh * a1.x, sh * a1.y, sh * a1.z, ch);
    float3 r = qrot(T.q, At);
    T.t.x += r.x; T.t.y += r.y; T.t.z += r.z;
    T.q = qmul(T.q, Aq);
}

// pose-first variant: T = P * exp(wk * delta), P given as (pt, pq)
__device__ __forceinline__ Xf step0(const float4 pt, const float4 pq,
                                    const float4 a0, const float4 a1,
                                    const float4 a2, const float4 a3,
                                    float wk) {
    Xf T;
    T.t = f3(pt.x, pt.y, pt.z);
    T.q = pq;
    stepc(T, a0, a1, a2, a3, wk);
    return T;
}

// ---------------------------------------------------------------------------
// Kernel 2: warp = (b, segment pair m -> segments 2m, 2m+1), lane = sample k.
// ---------------------------------------------------------------------------
__global__ void __launch_bounds__(256) k_spline(const float* __restrict__ timev,
                                                float* __restrict__ out) {
    int w    = threadIdx.x >> 5;
    int lane = threadIdx.x & 31;
    int gp = blockIdx.x * 8 + w;
    if (gp >= LS_B * LS_M) return;
    int b = gp >> 10;
    int m = gp & (LS_M - 1);
    int s0 = 2 * m;
    bool tail = (s0 + 1 >= LS_S);

    float u  = __ldg(timev + lane);
    float u2 = u * u;
    float u3 = u2 * u;
    const float w0 = (5.0f + 3.0f * u - 3.0f * u2 + u3) * (1.0f / 6.0f);
    const float w1 = (1.0f + 3.0f * u + 3.0f * u2 - 2.0f * u3) * (1.0f / 6.0f);
    const float w2 = u3 * (1.0f / 6.0f);

    const float4* R = g_pre + ((size_t)b * LS_J + s0) * REC;

    // --- record s0: T0 = P0 * exp(w0 * d0)
    Xf T0;
    {
        float4 a0 = R[0], a1 = R[1], a2 = R[2], a3 = R[3];
        float4 pt = R[4], pq = R[5];
        T0 = step0(pt, pq, a0, a1, a2, a3, w0);
    }
    // --- record s0+1: T1 = P1 * exp(w0 * d1); T0 *= exp(w1 * d1)
    Xf T1;
    {
        const float4* Rr = R + REC;
        float4 a0 = Rr[0], a1 = Rr[1], a2 = Rr[2], a3 = Rr[3];
        float4 pt = Rr[4], pq = Rr[5];
        T1 = step0(pt, pq, a0, a1, a2, a3, w0);
        stepc(T0, a0, a1, a2, a3, w1);
    }
    // --- record s0+2: T0 *= exp(w2 * d2)  (final); T1 *= exp(w1 * d2)
    {
        const float4* Rr = R + 2 * REC;
        float4 a0 = Rr[0], a1 = Rr[1], a2 = Rr[2], a3 = Rr[3];
        stepc(T0, a0, a1, a2, a3, w2);
        stepc(T1, a0, a1, a2, a3, w1);
    }
    // --- record s0+3 (clamped on tail): T1 *= exp(w2 * d3)  (final)
    {
        const float4* Rr = R + (tail ? 2 : 3) * REC;
        float4 a0 = Rr[0], a1 = Rr[1], a2 = Rr[2], a3 = Rr[3];
        stepc(T1, a0, a1, a2, a3, w2);
    }

    // stage through shared; 448 contiguous floats per warp
    __shared__ __align__(16) float sm[8 * 448];
    float* smw  = sm + w * 448;
    float* smw2 = smw + 224;
    int o7 = lane * 7;
    smw[o7 + 0] = T0.t.x; smw[o7 + 1] = T0.t.y; smw[o7 + 2] = T0.t.z;
    smw[o7 + 3] = T0.q.x; smw[o7 + 4] = T0.q.y; smw[o7 + 5] = T0.q.z; smw[o7 + 6] = T0.q.w;
    smw2[o7 + 0] = T1.t.x; smw2[o7 + 1] = T1.t.y; smw2[o7 + 2] = T1.t.z;
    smw2[o7 + 3] = T1.q.x; smw2[o7 + 4] = T1.q.y; smw2[o7 + 5] = T1.q.z; smw2[o7 + 6] = T1.q.w;
    __syncwarp();

    const float4* sm4 = (const float4*)smw;
    size_t pair0 = (size_t)b * LS_S + s0;
    float4* ob4 = (float4*)(out + pair0 * 224);
    if (!tail) {
        ob4[lane]      = sm4[lane];
        ob4[lane + 32] = sm4[lane + 32];
        ob4[lane + 64] = sm4[lane + 64];
        if (lane < 16) ob4[lane + 96] = sm4[lane + 96];
    } else {
        ob4[lane] = sm4[lane];
        if (lane < 24) ob4[lane + 32] = sm4[lane + 32];
    }
}

extern "C" void kernel_launch(void* const* d_in, const int* in_sizes, int n_in,
                              void* d_out, int out_size) {
    (void)n_in; (void)out_size;
    const float* poses = (const float*)d_in[0];
    const float* timev = (const float*)d_in[1];
    float* out = (float*)d_out;

    int tot1 = LS_B * LS_J;
    k_delta<<<(tot1 + 255) / 256, 256>>>(poses);

    int tot2 = LS_B * LS_M;
    k_spline<<<(tot2 + 7) / 8, 256>>>(timev, out);
}